// round 14
// baseline (speedup 1.0000x reference)
#include <cuda_runtime.h>
#include <cstddef>

#define ALPHA_ 0.0001f
#define NN 16
#define TT 8
#define VV 256
#define FF 64
#define NVV (NN*VV*VV)
#define YS 68               // padded row stride: conflict-free column reads
#define NBLK 288            // 18 x 16; <=296 co-resident at 2 CTAs/SM

__device__ float g_sloss[NBLK];
__device__ float g_dloss[NN];
__device__ float g_colsum[NN * VV];
__device__ unsigned int g_c1 = 0, g_counter = 0;
__device__ volatile unsigned int g_r1 = 0;

// grid (18, 16), 512 threads, __launch_bounds__(512,2) -> <=64 regs, 2
// CTAs/SM guaranteed -> all 288 blocks co-resident (barrier-safe) and 8
// warps/SMSP for latency coverage. Symmetric exp(score): only 36 upper
// 32x32 tiles computed; block owns 2 tiles, 8 warps/tile, warp owns a
// 4-column strip, thread tile 4i x 1j. e stays in registers across ONE
// grid barrier; phase C writes S to (i,j) and (j,i).
extern "C" __global__ void __launch_bounds__(512, 2)
fused_kernel(const float* __restrict__ x, const float* __restrict__ a,
             float* __restrict__ out) {
    extern __shared__ float y[];            // [256][YS] y = xm*a (~68KB)
    __shared__ float red[512];
    __shared__ float Ts[VV];                // row sums of y (max-trick)
    __shared__ float colpart[VV];
    __shared__ float invs[VV];
    __shared__ float sqw[16];
    __shared__ float wsum[16];
    __shared__ unsigned int s_flag;

    const int tid  = threadIdx.x;
    const int lane = tid & 31;
    const int w    = tid >> 5;
    const int lj   = lane & 3;              // j within 4-col strip
    const int li8  = lane >> 2;             // 0..7, i rows li8 + 8k
    const int b    = blockIdx.x;            // 0..17
    const int n    = blockIdx.y;
    const float* __restrict__ xm = x + (size_t)(n * TT + TT / 2) * (VV * FF);
    float* __restrict__ on = out + (size_t)n * (VV * VV);

    // Stage y = xm * a (tid&63 = fixed feature -> free per-f raw sums).
    const int   f  = tid & 63;
    const float af = __ldg(&a[f]);
    float Sx = 0.f, Sq = 0.f;
#pragma unroll
    for (int k = 0; k < 32; ++k) {
        int idx = tid + (k << 9);
        float v = xm[idx];
        y[(idx >> 6) * YS + f] = v * af;
        Sx += v;
        Sq = fmaf(v, v, Sq);
    }
    red[tid] = Sx;
#pragma unroll
    for (int o = 16; o; o >>= 1) Sq += __shfl_down_sync(~0u, Sq, o);
    if (lane == 0) sqw[w] = Sq;
    if (tid < VV) colpart[tid] = 0.f;
    __syncthreads();

    // Row sums T_r (one-time).
    if (tid < VV) {
        const float4* p = reinterpret_cast<const float4*>(&y[tid * YS]);
        float s0 = 0.f, s1 = 0.f, s2 = 0.f, s3 = 0.f;
#pragma unroll
        for (int k = 0; k < 16; k += 4) {
            float4 v0 = p[k], v1 = p[k + 1], v2 = p[k + 2], v3 = p[k + 3];
            s0 += v0.x + v0.y + v0.z + v0.w;
            s1 += v1.x + v1.y + v1.z + v1.w;
            s2 += v2.x + v2.y + v2.z + v2.w;
            s3 += v3.x + v3.y + v3.z + v3.w;
        }
        Ts[tid] = (s0 + s1) + (s2 + s3);
    }

    // dloss_n = 2*(V*sum x^2 - sum_f (sum_i x)^2); valid since S's column
    // sums are exactly 1 (softmax axis) -> sum(S@d2) == sum(d2).
    if (b == 0 && w == 8) {
        float s1 = 0.f, s2 = 0.f;
#pragma unroll
        for (int r2 = 0; r2 < 8; ++r2) {
            s1 += red[lane + (r2 << 6)];
            s2 += red[lane + 32 + (r2 << 6)];
        }
        float t  = s1 * s1 + s2 * s2;
        float sq = (lane < 16) ? sqw[lane] : 0.f;
#pragma unroll
        for (int o = 16; o; o >>= 1) {
            t  += __shfl_down_sync(~0u, t, o);
            sq += __shfl_down_sync(~0u, sq, o);
        }
        if (lane == 0) __stcg(&g_dloss[n], 2.f * ((float)VV * sq - t));
    }
    __syncthreads();

    // ---- Phase A: warp's tile (r, c), r <= c, 4-col strip q.
    int t = b * 2 + (w >> 3);
    int r = 0;
    while (t >= 8 - r) { t -= 8 - r; ++r; }
    const int c  = r + t;
    const int q  = w & 7;
    const int cj = c * 32 + q * 4 + lj;     // this thread's column

    const float* __restrict__ xib = y + (r * 32 + li8) * YS;   // +8k*YS
    const float* __restrict__ xjb = y + cj * YS;

    float acc[4] = {0.f, 0.f, 0.f, 0.f};
#pragma unroll 4
    for (int h = 0; h < 16; ++h) {
        float4 xj = *reinterpret_cast<const float4*>(xjb + h * 4);
        float4 xi[4];
#pragma unroll
        for (int k = 0; k < 4; ++k)
            xi[k] = *reinterpret_cast<const float4*>(xib + k * 8 * YS + h * 4);
#pragma unroll
        for (int k = 0; k < 4; ++k) {
            float s = acc[k];
            s += fmaxf(xi[k].x, xj.x);       // FMNMX (alu) + FADD (fma)
            s += fmaxf(xi[k].y, xj.y);
            s += fmaxf(xi[k].z, xj.z);
            s += fmaxf(xi[k].w, xj.w);
            acc[k] = s;
        }
    }

    // score = 2*acc - Ti - Tj (>= 0: relu identity); exp + partials.
    const float Tjv = Ts[cj];
    float e[4];
    float cp = 0.f;
#pragma unroll
    for (int k = 0; k < 4; ++k) {
        float v = __expf(2.f * acc[k] - Ts[r * 32 + li8 + 8 * k] - Tjv);
        e[k] = v;
        cp += v;
    }
    // Column partial: reduce over li8 (xor 4,8,16 keeps lj class).
#pragma unroll
    for (int o = 4; o < 32; o <<= 1) cp += __shfl_xor_sync(~0u, cp, o);
    if (lane < 4) atomicAdd(&colpart[c * 32 + q * 4 + lane], cp);

    // Row sums = colsums of mirrored tile (off-diagonal only).
    if (r != c) {
        float rp[4];
#pragma unroll
        for (int k = 0; k < 4; ++k) rp[k] = e[k];
#pragma unroll
        for (int o = 1; o < 4; o <<= 1)
#pragma unroll
            for (int k = 0; k < 4; ++k)
                rp[k] += __shfl_xor_sync(~0u, rp[k], o);
        if (lj == 0)
#pragma unroll
            for (int k = 0; k < 4; ++k)
                atomicAdd(&colpart[r * 32 + li8 + 8 * k], rp[k]);
    }
    __syncthreads();
    if (tid < VV) {
        atomicAdd(&g_colsum[n * VV + tid], colpart[tid]);
        __threadfence();                     // publish before barrier
    }

    // ---- Single grid barrier (all 288 blocks co-resident by construction).
    __syncthreads();
    if (tid == 0) {
        __threadfence();
        if (atomicAdd(&g_c1, 1u) == NBLK - 1) g_r1 = 1u;
        else while (g_r1 == 0u) __nanosleep(64);
        __threadfence();
    }
    __syncthreads();

    if (tid < VV) invs[tid] = 1.0f / __ldcg(&g_colsum[n * VV + tid]);
    __syncthreads();

    // ---- Phase C: normalize FROM REGISTERS; write direct + mirror.
    const float ivc = invs[cj];
    float sq2 = 0.f;
#pragma unroll
    for (int k = 0; k < 4; ++k) {
        const int gi = r * 32 + li8 + 8 * k;
        float S = e[k] * ivc;
        on[(size_t)gi * VV + cj] = S;        // 16B-coalesced groups
        sq2 = fmaf(S, S, sq2);
        if (r != c) {
            float Mv = e[k] * invs[gi];
            on[(size_t)cj * VV + gi] = Mv;   // 32B-coalesced groups
            sq2 = fmaf(Mv, Mv, sq2);
        }
    }
#pragma unroll
    for (int o = 16; o; o >>= 1) sq2 += __shfl_down_sync(~0u, sq2, o);
    if (lane == 0) wsum[w] = sq2;
    __syncthreads();

    // ---- Last-block finalize (graph-safe: ALL state reset each call).
    const int bid = n * 18 + b;
    if (tid == 0) {
        float tt = 0.f;
#pragma unroll
        for (int k = 0; k < 16; ++k) tt += wsum[k];
        __stcg(&g_sloss[bid], tt);
        __threadfence();
        unsigned int cdone = atomicAdd(&g_counter, 1u);
        s_flag = (cdone == NBLK - 1) ? 1u : 0u;
    }
    __syncthreads();
    if (s_flag) {
        for (int idx = tid; idx < NN * VV; idx += 512)
            __stcg(&g_colsum[idx], 0.f);     // reset for next replay
        if (w == 0) {
            __threadfence();
            float s = 0.f;
#pragma unroll
            for (int k = 0; k < 9; ++k)      // 288 = 9 * 32
                s += __ldcg(&g_sloss[lane + (k << 5)]);
            float dl = (lane < NN) ? __ldcg(&g_dloss[lane]) : 0.f;
#pragma unroll
            for (int o = 16; o; o >>= 1) {
                s  += __shfl_down_sync(~0u, s, o);
                dl += __shfl_down_sync(~0u, dl, o);
            }
            if (lane == 0) {
                out[NVV]     = s * (ALPHA_ / (float)NN);
                out[NVV + 1] = dl * ALPHA_;
                g_c1 = 0; g_r1 = 0; g_counter = 0;   // reset barrier state
            }
        }
    }
}

extern "C" void kernel_launch(void* const* d_in, const int* in_sizes, int n_in,
                              void* d_out, int out_size) {
    const float* x = (const float*)d_in[0];
    const float* a = (const float*)d_in[1];
    if (n_in >= 2 && in_sizes[0] == FF) {      // defensive input-order check
        const float* t = x; x = a; a = t;
    }
    float* out = (float*)d_out;

    const int smem = VV * YS * (int)sizeof(float);
    cudaFuncSetAttribute(fused_kernel,
                         cudaFuncAttributeMaxDynamicSharedMemorySize, smem);
    fused_kernel<<<dim3(18, NN), 512, smem>>>(x, a, out);
}

// round 15
// speedup vs baseline: 1.1345x; 1.1345x over previous
#include <cuda_runtime.h>
#include <cstddef>

#define ALPHA_ 0.0001f
#define NN 16
#define TT 8
#define VV 256
#define FF 64
#define NVV (NN*VV*VV)
#define YS 68               // padded row stride: conflict-free column reads
#define NBLK 144            // 9 x 16; <=148 SMs -> co-resident, barrier-safe

__device__ float g_sloss[NBLK];
__device__ float g_dloss[NN];
__device__ float g_cspart[NN * 9 * VV];   // per-block colsum partials (no reset needed)
__device__ unsigned int g_c1 = 0, g_counter = 0;
__device__ volatile unsigned int g_r1 = 0;

// grid (9, 16), 512 threads, 1 CTA/SM, all 144 blocks co-resident.
// Symmetric exp(score): only the 36 upper 32x32 tiles computed. Warp w owns
// tile t=b*4+(w>>2) and an 8-col strip; thread tile 4i x 2j. e stays in
// registers across ONE grid barrier; phase C writes S to (i,j) AND (j,i).
// vs R13: conflict-free Ts, no global atomics (per-block partial slices,
// nothing to reset), prefetch-pipelined main loop.
extern "C" __global__ void __launch_bounds__(512, 1)
fused_kernel(const float* __restrict__ x, const float* __restrict__ a,
             float* __restrict__ out) {
    extern __shared__ float y[];            // [256][YS] y = xm*a (~68KB)
    __shared__ float red[512];
    __shared__ float Ts[VV];                // row sums of y (max-trick)
    __shared__ float colpart[VV];           // block-local colsum partials
    __shared__ float invs[VV];
    __shared__ float sqw[16];
    __shared__ float wsum[16];
    __shared__ unsigned int s_flag;

    const int tid  = threadIdx.x;
    const int lane = tid & 31;
    const int w    = tid >> 5;
    const int li   = lane & 7;
    const int g4   = lane >> 3;             // 0..3
    const int b    = blockIdx.x;            // 0..8
    const int n    = blockIdx.y;
    const float* __restrict__ xm = x + (size_t)(n * TT + TT / 2) * (VV * FF);
    float* __restrict__ on = out + (size_t)n * (VV * VV);

    // Stage y = xm * a (tid&63 = fixed feature -> free per-f raw sums).
    const int   f  = tid & 63;
    const float af = __ldg(&a[f]);
    float Sx = 0.f, Sq = 0.f;
#pragma unroll
    for (int k = 0; k < 32; ++k) {
        int idx = tid + (k << 9);
        float v = xm[idx];
        y[(idx >> 6) * YS + f] = v * af;
        Sx += v;
        Sq = fmaf(v, v, Sq);
    }
    red[tid] = Sx;
#pragma unroll
    for (int o = 16; o; o >>= 1) Sq += __shfl_down_sync(~0u, Sq, o);
    if (lane == 0) sqw[w] = Sq;
    if (tid < VV) colpart[tid] = 0.f;
    __syncthreads();

    // Row sums T_r: warp w sums rows [16w,16w+16). Lanes read consecutive
    // float2 (64 floats by 32 lanes) -> conflict-free; shfl-reduce.
    {
        const int r0 = w << 4;
#pragma unroll
        for (int rr = 0; rr < 16; ++rr) {
            float2 v = *reinterpret_cast<const float2*>(
                &y[(r0 + rr) * YS + lane * 2]);
            float s = v.x + v.y;
#pragma unroll
            for (int o = 16; o; o >>= 1) s += __shfl_down_sync(~0u, s, o);
            if (lane == 0) Ts[r0 + rr] = s;
        }
    }

    // dloss_n = 2*(V*sum x^2 - sum_f (sum_i x)^2); valid since S's column
    // sums are exactly 1 (softmax axis) -> sum(S@d2) == sum(d2).
    if (b == 0 && w == 8) {
        float s1 = 0.f, s2 = 0.f;
#pragma unroll
        for (int r2 = 0; r2 < 8; ++r2) {
            s1 += red[lane + (r2 << 6)];
            s2 += red[lane + 32 + (r2 << 6)];
        }
        float t  = s1 * s1 + s2 * s2;
        float sq = (lane < 16) ? sqw[lane] : 0.f;
#pragma unroll
        for (int o = 16; o; o >>= 1) {
            t  += __shfl_down_sync(~0u, t, o);
            sq += __shfl_down_sync(~0u, sq, o);
        }
        if (lane == 0) __stcg(&g_dloss[n], 2.f * ((float)VV * sq - t));
    }
    __syncthreads();

    // ---- Phase A: warp's tile (r, c), r <= c, from triangle unrank.
    int t = b * 4 + (w >> 2);
    int r = 0;
    while (t >= 8 - r) { t -= 8 - r; ++r; }
    const int c  = r + t;
    const int c0 = ((w & 3) << 3) + (g4 << 1);  // col offset in tile (+0,+1)

    const float* __restrict__ xib = y + (r * 32 + li) * YS;   // +8k*YS
    const float* __restrict__ xjb = y + (c * 32 + c0) * YS;   // +m*YS

    float acc[8];
#pragma unroll
    for (int p = 0; p < 8; ++p) acc[p] = 0.f;

    // Prefetch-pipelined main loop (h=15 over-read lands in row padding).
    float4 cxi[4], cxj[2];
#pragma unroll
    for (int k = 0; k < 4; ++k)
        cxi[k] = *reinterpret_cast<const float4*>(xib + k * 8 * YS);
#pragma unroll
    for (int m = 0; m < 2; ++m)
        cxj[m] = *reinterpret_cast<const float4*>(xjb + m * YS);

#pragma unroll 4
    for (int h = 0; h < 16; ++h) {
        float4 nxi[4], nxj[2];
#pragma unroll
        for (int k = 0; k < 4; ++k)
            nxi[k] = *reinterpret_cast<const float4*>(xib + k * 8 * YS + h * 4 + 4);
#pragma unroll
        for (int m = 0; m < 2; ++m)
            nxj[m] = *reinterpret_cast<const float4*>(xjb + m * YS + h * 4 + 4);
#pragma unroll
        for (int k = 0; k < 4; ++k)
#pragma unroll
            for (int m = 0; m < 2; ++m) {
                float s = acc[k * 2 + m];
                s += fmaxf(cxi[k].x, cxj[m].x);  // FMNMX (alu) + FADD (fma)
                s += fmaxf(cxi[k].y, cxj[m].y);
                s += fmaxf(cxi[k].z, cxj[m].z);
                s += fmaxf(cxi[k].w, cxj[m].w);
                acc[k * 2 + m] = s;
            }
#pragma unroll
        for (int k = 0; k < 4; ++k) cxi[k] = nxi[k];
#pragma unroll
        for (int m = 0; m < 2; ++m) cxj[m] = nxj[m];
    }

    // score = 2*acc - Ti - Tj (>= 0: relu identity); exp.
    float Ti[4], Tj[2];
#pragma unroll
    for (int k = 0; k < 4; ++k) Ti[k] = Ts[r * 32 + li + 8 * k];
#pragma unroll
    for (int m = 0; m < 2; ++m) Tj[m] = Ts[c * 32 + c0 + m];

    float e[8];
    float cp0 = 0.f, cp1 = 0.f;
#pragma unroll
    for (int k = 0; k < 4; ++k) {
        float v0 = __expf(2.f * acc[k * 2]     - Ti[k] - Tj[0]);
        float v1 = __expf(2.f * acc[k * 2 + 1] - Ti[k] - Tj[1]);
        e[k * 2] = v0; e[k * 2 + 1] = v1;
        cp0 += v0; cp1 += v1;
    }
    // Column partials: reduce over li (xor 1,2,4 stays in 8-lane group).
#pragma unroll
    for (int o = 1; o < 8; o <<= 1) {
        cp0 += __shfl_xor_sync(~0u, cp0, o);
        cp1 += __shfl_xor_sync(~0u, cp1, o);
    }
    if (li == 0) {
        atomicAdd(&colpart[c * 32 + c0],     cp0);
        atomicAdd(&colpart[c * 32 + c0 + 1], cp1);
    }
    // Row sums double as colsums of the mirrored tile (off-diag only).
    if (r != c) {
        float rp[4];
#pragma unroll
        for (int k = 0; k < 4; ++k) rp[k] = e[k * 2] + e[k * 2 + 1];
#pragma unroll
        for (int o = 8; o < 32; o <<= 1)
#pragma unroll
            for (int k = 0; k < 4; ++k)
                rp[k] += __shfl_xor_sync(~0u, rp[k], o);
        if (lane < 8)
#pragma unroll
            for (int k = 0; k < 4; ++k)
                atomicAdd(&colpart[r * 32 + li + 8 * k], rp[k]);
    }
    __syncthreads();
    // Publish this block's partial slice (plain store: overwritten each
    // call -> nothing to reset for graph replay).
    if (tid < VV) {
        __stcg(&g_cspart[(n * 9 + b) * VV + tid], colpart[tid]);
        __threadfence();
    }

    // ---- Single grid barrier (all 144 blocks co-resident).
    __syncthreads();
    if (tid == 0) {
        __threadfence();
        if (atomicAdd(&g_c1, 1u) == NBLK - 1) g_r1 = 1u;
        else while (g_r1 == 0u) __nanosleep(64);
        __threadfence();
    }
    __syncthreads();

    if (tid < VV) {
        float s = 0.f;
#pragma unroll
        for (int p = 0; p < 9; ++p)
            s += __ldcg(&g_cspart[(n * 9 + p) * VV + tid]);
        invs[tid] = 1.0f / s;
    }
    __syncthreads();

    // ---- Phase C: normalize FROM REGISTERS; write direct + mirror.
    float ivc0 = invs[c * 32 + c0], ivc1 = invs[c * 32 + c0 + 1];
    float ivr[4];
#pragma unroll
    for (int k = 0; k < 4; ++k) ivr[k] = invs[r * 32 + li + 8 * k];

    float sq2 = 0.f;
#pragma unroll
    for (int k = 0; k < 4; ++k) {
        const int gi = r * 32 + li + 8 * k;
        float S0 = e[k * 2] * ivc0, S1 = e[k * 2 + 1] * ivc1;
        *reinterpret_cast<float2*>(on + (size_t)gi * VV + c * 32 + c0) =
            make_float2(S0, S1);
        sq2 = fmaf(S0, S0, fmaf(S1, S1, sq2));
        if (r != c) {
            float M0 = e[k * 2] * ivr[k], M1 = e[k * 2 + 1] * ivr[k];
            on[(size_t)(c * 32 + c0)     * VV + gi] = M0;
            on[(size_t)(c * 32 + c0 + 1) * VV + gi] = M1;
            sq2 = fmaf(M0, M0, fmaf(M1, M1, sq2));
        }
    }
#pragma unroll
    for (int o = 16; o; o >>= 1) sq2 += __shfl_down_sync(~0u, sq2, o);
    if (lane == 0) wsum[w] = sq2;
    __syncthreads();

    // ---- Last-block finalize (graph-safe: barrier/counter state reset).
    const int bid = n * 9 + b;
    if (tid == 0) {
        float tt = 0.f;
#pragma unroll
        for (int k = 0; k < 16; ++k) tt += wsum[k];
        __stcg(&g_sloss[bid], tt);
        __threadfence();
        unsigned int cdone = atomicAdd(&g_counter, 1u);
        s_flag = (cdone == NBLK - 1) ? 1u : 0u;
    }
    __syncthreads();
    if (s_flag && w == 0) {
        __threadfence();
        float s = 0.f;
#pragma unroll
        for (int k = 0; k < 5; ++k) {
            int idx = lane + (k << 5);
            if (idx < NBLK) s += __ldcg(&g_sloss[idx]);
        }
        float dl = (lane < NN) ? __ldcg(&g_dloss[lane]) : 0.f;
#pragma unroll
        for (int o = 16; o; o >>= 1) {
            s  += __shfl_down_sync(~0u, s, o);
            dl += __shfl_down_sync(~0u, dl, o);
        }
        if (lane == 0) {
            out[NVV]     = s * (ALPHA_ / (float)NN);
            out[NVV + 1] = dl * ALPHA_;
            g_c1 = 0; g_r1 = 0; g_counter = 0;   // reset barrier state
        }
    }
}

extern "C" void kernel_launch(void* const* d_in, const int* in_sizes, int n_in,
                              void* d_out, int out_size) {
    const float* x = (const float*)d_in[0];
    const float* a = (const float*)d_in[1];
    if (n_in >= 2 && in_sizes[0] == FF) {      // defensive input-order check
        const float* t = x; x = a; a = t;
    }
    float* out = (float*)d_out;

    const int smem = VV * YS * (int)sizeof(float);
    cudaFuncSetAttribute(fused_kernel,
                         cudaFuncAttributeMaxDynamicSharedMemorySize, smem);
    fused_kernel<<<dim3(9, NN), 512, smem>>>(x, a, out);
}

// round 16
// speedup vs baseline: 1.2854x; 1.1330x over previous
#include <cuda_runtime.h>
#include <cstddef>

#define ALPHA_ 0.0001f
#define NN 16
#define TT 8
#define VV 256
#define FF 64
#define NVV (NN*VV*VV)
#define YS 68               // padded row stride: conflict-free column reads
#define NBLK 144            // 9 x 16; <=148 SMs -> co-resident, barrier-safe

__device__ float g_sloss[NBLK];
__device__ float g_dloss[NN];
__device__ float g_colsum[NN * VV];
__device__ unsigned int g_c1 = 0, g_counter = 0;
__device__ volatile unsigned int g_r1 = 0;

// grid (9, 16), 512 threads, 1 CTA/SM, all 144 blocks co-resident.
// Symmetric exp(score): only the 36 upper 32x32 tiles computed (0.56x
// pairs). Warp w owns tile t=b*4+(w>>2), an 8-col strip (w&3); thread tile
// 4i x 2j. e stays in registers across ONE grid barrier; phase C
// normalizes from registers and writes S to (i,j) AND (j,i).
extern "C" __global__ void __launch_bounds__(512, 1)
fused_kernel(const float* __restrict__ x, const float* __restrict__ a,
             float* __restrict__ out) {
    extern __shared__ float y[];            // [256][YS] y = xm*a (~68KB)
    __shared__ float red[512];
    __shared__ float Ts[VV];                // row sums of y (max-trick)
    __shared__ float colpart[VV];           // block-local colsum partials
    __shared__ float invs[VV];
    __shared__ float sqw[16];
    __shared__ float wsum[16];
    __shared__ unsigned int s_flag;

    const int tid  = threadIdx.x;
    const int lane = tid & 31;
    const int w    = tid >> 5;
    const int li   = lane & 7;
    const int g4   = lane >> 3;             // 0..3
    const int b    = blockIdx.x;            // 0..8
    const int n    = blockIdx.y;
    const float* __restrict__ xm = x + (size_t)(n * TT + TT / 2) * (VV * FF);
    float* __restrict__ on = out + (size_t)n * (VV * VV);

    // Stage y = xm * a (tid&63 = fixed feature -> free per-f raw sums).
    const int   f  = tid & 63;
    const float af = __ldg(&a[f]);
    float Sx = 0.f, Sq = 0.f;
#pragma unroll
    for (int k = 0; k < 32; ++k) {
        int idx = tid + (k << 9);
        float v = xm[idx];
        y[(idx >> 6) * YS + f] = v * af;
        Sx += v;
        Sq = fmaf(v, v, Sq);
    }
    // dloss prep only where it's consumed (b == 0).
    if (b == 0) {
        red[tid] = Sx;
#pragma unroll
        for (int o = 16; o; o >>= 1) Sq += __shfl_down_sync(~0u, Sq, o);
        if (lane == 0) sqw[w] = Sq;
    }
    if (tid < VV) colpart[tid] = 0.f;
    __syncthreads();

    // Row sums T_r (one-time; float4 at stride 17 quads -> conflict-free).
    if (tid < VV) {
        const float4* p = reinterpret_cast<const float4*>(&y[tid * YS]);
        float s0 = 0.f, s1 = 0.f, s2 = 0.f, s3 = 0.f;
#pragma unroll
        for (int k = 0; k < 16; k += 4) {
            float4 v0 = p[k], v1 = p[k + 1], v2 = p[k + 2], v3 = p[k + 3];
            s0 += v0.x + v0.y + v0.z + v0.w;
            s1 += v1.x + v1.y + v1.z + v1.w;
            s2 += v2.x + v2.y + v2.z + v2.w;
            s3 += v3.x + v3.y + v3.z + v3.w;
        }
        Ts[tid] = (s0 + s1) + (s2 + s3);
    }

    // dloss_n = 2*(V*sum x^2 - sum_f (sum_i x)^2); valid since S's column
    // sums are exactly 1 (softmax axis) -> sum(S@d2) == sum(d2).
    if (b == 0 && w == 8) {
        float s1 = 0.f, s2 = 0.f;
#pragma unroll
        for (int r2 = 0; r2 < 8; ++r2) {
            s1 += red[lane + (r2 << 6)];
            s2 += red[lane + 32 + (r2 << 6)];
        }
        float t  = s1 * s1 + s2 * s2;
        float sq = (lane < 16) ? sqw[lane] : 0.f;
#pragma unroll
        for (int o = 16; o; o >>= 1) {
            t  += __shfl_down_sync(~0u, t, o);
            sq += __shfl_down_sync(~0u, sq, o);
        }
        if (lane == 0) __stcg(&g_dloss[n], 2.f * ((float)VV * sq - t));
    }
    __syncthreads();

    // ---- Phase A: warp's tile (r, c), r <= c, from triangle unrank.
    int t = b * 4 + (w >> 2);
    int r = 0;
    while (t >= 8 - r) { t -= 8 - r; ++r; }
    const int c  = r + t;
    const int c0 = ((w & 3) << 3) + (g4 << 1);  // col offset in tile (+0,+1)

    const float* __restrict__ xib = y + (r * 32 + li) * YS;   // +8k*YS
    const float* __restrict__ xjb = y + (c * 32 + c0) * YS;   // +m*YS

    float acc[8];
#pragma unroll
    for (int p = 0; p < 8; ++p) acc[p] = 0.f;

#pragma unroll 8
    for (int h = 0; h < 16; ++h) {
        float4 xi[4], xj[2];
#pragma unroll
        for (int k = 0; k < 4; ++k)
            xi[k] = *reinterpret_cast<const float4*>(xib + k * 8 * YS + h * 4);
#pragma unroll
        for (int m = 0; m < 2; ++m)
            xj[m] = *reinterpret_cast<const float4*>(xjb + m * YS + h * 4);
#pragma unroll
        for (int k = 0; k < 4; ++k)
#pragma unroll
            for (int m = 0; m < 2; ++m) {
                float s = acc[k * 2 + m];
                s += fmaxf(xi[k].x, xj[m].x);    // FMNMX (alu) + FADD (fma)
                s += fmaxf(xi[k].y, xj[m].y);
                s += fmaxf(xi[k].z, xj[m].z);
                s += fmaxf(xi[k].w, xj[m].w);
                acc[k * 2 + m] = s;
            }
    }

    // score = 2*acc - Ti - Tj (>= 0: relu identity); exp.
    float Ti[4], Tj[2];
#pragma unroll
    for (int k = 0; k < 4; ++k) Ti[k] = Ts[r * 32 + li + 8 * k];
#pragma unroll
    for (int m = 0; m < 2; ++m) Tj[m] = Ts[c * 32 + c0 + m];

    float e[8];
    float cp0 = 0.f, cp1 = 0.f;
#pragma unroll
    for (int k = 0; k < 4; ++k) {
        float v0 = __expf(2.f * acc[k * 2]     - Ti[k] - Tj[0]);
        float v1 = __expf(2.f * acc[k * 2 + 1] - Ti[k] - Tj[1]);
        e[k * 2] = v0; e[k * 2 + 1] = v1;
        cp0 += v0; cp1 += v1;
    }
    // Column partials: reduce over li (xor 1,2,4 stays in 8-lane group).
#pragma unroll
    for (int o = 1; o < 8; o <<= 1) {
        cp0 += __shfl_xor_sync(~0u, cp0, o);
        cp1 += __shfl_xor_sync(~0u, cp1, o);
    }
    if (li == 0) {
        atomicAdd(&colpart[c * 32 + c0],     cp0);
        atomicAdd(&colpart[c * 32 + c0 + 1], cp1);
    }
    // Row sums double as colsums of the mirrored tile (off-diag only).
    if (r != c) {
        float rp[4];
#pragma unroll
        for (int k = 0; k < 4; ++k) rp[k] = e[k * 2] + e[k * 2 + 1];
#pragma unroll
        for (int o = 8; o < 32; o <<= 1)
#pragma unroll
            for (int k = 0; k < 4; ++k)
                rp[k] += __shfl_xor_sync(~0u, rp[k], o);
        if (lane < 8)
#pragma unroll
            for (int k = 0; k < 4; ++k)
                atomicAdd(&colpart[r * 32 + li + 8 * k], rp[k]);
    }
    __syncthreads();
    if (tid < VV) {
        atomicAdd(&g_colsum[n * VV + tid], colpart[tid]);
        __threadfence();                     // publish before barrier
    }

    // ---- Single grid barrier (all 144 blocks co-resident).
    if (tid == 0) {
        __threadfence();
        if (atomicAdd(&g_c1, 1u) == NBLK - 1) g_r1 = 1u;
        else while (g_r1 == 0u) __nanosleep(64);
        __threadfence();
    }
    __syncthreads();

    if (tid < VV) invs[tid] = 1.0f / __ldcg(&g_colsum[n * VV + tid]);
    __syncthreads();

    // ---- Phase C: normalize FROM REGISTERS; write direct + mirror.
    float ivc0 = invs[c * 32 + c0], ivc1 = invs[c * 32 + c0 + 1];
    float ivr[4];
#pragma unroll
    for (int k = 0; k < 4; ++k) ivr[k] = invs[r * 32 + li + 8 * k];

    float sq2 = 0.f;
#pragma unroll
    for (int k = 0; k < 4; ++k) {
        const int gi = r * 32 + li + 8 * k;
        float S0 = e[k * 2] * ivc0, S1 = e[k * 2 + 1] * ivc1;
        *reinterpret_cast<float2*>(on + (size_t)gi * VV + c * 32 + c0) =
            make_float2(S0, S1);
        sq2 = fmaf(S0, S0, fmaf(S1, S1, sq2));
        if (r != c) {
            float M0 = e[k * 2] * ivr[k], M1 = e[k * 2 + 1] * ivr[k];
            on[(size_t)(c * 32 + c0)     * VV + gi] = M0;
            on[(size_t)(c * 32 + c0 + 1) * VV + gi] = M1;
            sq2 = fmaf(M0, M0, fmaf(M1, M1, sq2));
        }
    }
#pragma unroll
    for (int o = 16; o; o >>= 1) sq2 += __shfl_down_sync(~0u, sq2, o);
    if (lane == 0) wsum[w] = sq2;
    __syncthreads();

    // ---- Last-block finalize (graph-safe: ALL state reset each call).
    const int bid = n * 9 + b;
    if (tid == 0) {
        float tt = 0.f;
#pragma unroll
        for (int k = 0; k < 16; ++k) tt += wsum[k];
        __stcg(&g_sloss[bid], tt);
        __threadfence();
        unsigned int cdone = atomicAdd(&g_counter, 1u);
        s_flag = (cdone == NBLK - 1) ? 1u : 0u;
    }
    __syncthreads();
    if (s_flag) {
        for (int idx = tid; idx < NN * VV; idx += 512)
            __stcg(&g_colsum[idx], 0.f);     // reset for next replay
        if (w == 0) {
            __threadfence();
            float s = 0.f;
#pragma unroll
            for (int k = 0; k < 5; ++k) {
                int idx = lane + (k << 5);
                if (idx < NBLK) s += __ldcg(&g_sloss[idx]);
            }
            float dl = (lane < NN) ? __ldcg(&g_dloss[lane]) : 0.f;
#pragma unroll
            for (int o = 16; o; o >>= 1) {
                s  += __shfl_down_sync(~0u, s, o);
                dl += __shfl_down_sync(~0u, dl, o);
            }
            if (lane == 0) {
                out[NVV]     = s * (ALPHA_ / (float)NN);
                out[NVV + 1] = dl * ALPHA_;
                g_c1 = 0; g_r1 = 0; g_counter = 0;   // reset barrier state
            }
        }
    }
}

extern "C" void kernel_launch(void* const* d_in, const int* in_sizes, int n_in,
                              void* d_out, int out_size) {
    const float* x = (const float*)d_in[0];
    const float* a = (const float*)d_in[1];
    if (n_in >= 2 && in_sizes[0] == FF) {      // defensive input-order check
        const float* t = x; x = a; a = t;
    }
    float* out = (float*)d_out;

    const int smem = VV * YS * (int)sizeof(float);
    cudaFuncSetAttribute(fused_kernel,
                         cudaFuncAttributeMaxDynamicSharedMemorySize, smem);
    fused_kernel<<<dim3(9, NN), 512, smem>>>(x, a, out);
}

// round 17
// speedup vs baseline: 1.2937x; 1.0065x over previous
#include <cuda_runtime.h>
#include <cstddef>

#define ALPHA_ 0.0001f
#define NN 16
#define TT 8
#define VV 256
#define FF 64
#define NVV (NN*VV*VV)
#define YS 68               // padded row stride: conflict-free column reads
#define NBLK 144            // 9 x 16; <=148 SMs -> co-resident, barrier-safe

__device__ float g_sloss[NBLK];
__device__ float g_dloss[NN];
__device__ float g_colsum[NN * VV];
__device__ unsigned int g_c1 = 0, g_counter = 0;
__device__ volatile unsigned int g_r1 = 0;

// grid (9, 16), 512 threads, 1 CTA/SM, all 144 blocks co-resident.
// Symmetric exp(score): only the 36 upper 32x32 tiles computed (0.56x
// pairs). Warp w owns tile t=b*4+(w>>2), an 8-col strip (w&3); thread tile
// 4i x 2j. e stays in registers across ONE grid barrier; phase C
// normalizes from registers and writes S to (i,j) AND (j,i).
// vs R16: b>0 blocks stage with float4 LDG/STS (4x fewer mem instrs; only
// b==0 needs the scalar fixed-feature layout for the dloss sums), and the
// score collapses to a single FMA.
extern "C" __global__ void __launch_bounds__(512, 1)
fused_kernel(const float* __restrict__ x, const float* __restrict__ a,
             float* __restrict__ out) {
    extern __shared__ float y[];            // [256][YS] y = xm*a (~68KB)
    __shared__ float red[512];
    __shared__ float Ts[VV];                // row sums of y (max-trick)
    __shared__ float colpart[VV];           // block-local colsum partials
    __shared__ float invs[VV];
    __shared__ float sqw[16];
    __shared__ float wsum[16];
    __shared__ unsigned int s_flag;

    const int tid  = threadIdx.x;
    const int lane = tid & 31;
    const int w    = tid >> 5;
    const int li   = lane & 7;
    const int g4   = lane >> 3;             // 0..3
    const int b    = blockIdx.x;            // 0..8
    const int n    = blockIdx.y;
    const float* __restrict__ xm = x + (size_t)(n * TT + TT / 2) * (VV * FF);
    float* __restrict__ on = out + (size_t)n * (VV * VV);

    if (b == 0) {
        // Scalar staging: tid&63 = fixed feature -> free per-f raw sums
        // for dloss (consumed only by this block).
        const int   f  = tid & 63;
        const float af = __ldg(&a[f]);
        float Sx = 0.f, Sq = 0.f;
#pragma unroll
        for (int k = 0; k < 32; ++k) {
            int idx = tid + (k << 9);
            float v = xm[idx];
            y[(idx >> 6) * YS + f] = v * af;
            Sx += v;
            Sq = fmaf(v, v, Sq);
        }
        red[tid] = Sx;
#pragma unroll
        for (int o = 16; o; o >>= 1) Sq += __shfl_down_sync(~0u, Sq, o);
        if (lane == 0) sqw[w] = Sq;
    } else {
        // Vectorized staging: 8x LDG.128 + 8x STS.128 per thread.
        const int f4   = (tid & 15) << 2;   // fixed 4-feature group
        const int rw0  = tid >> 4;          // base row (0..31), +32 per k
        const float4 a4 = __ldg(reinterpret_cast<const float4*>(a) + (tid & 15));
#pragma unroll
        for (int k = 0; k < 8; ++k) {
            float4 v = *reinterpret_cast<const float4*>(
                xm + ((rw0 + (k << 5)) << 6) + f4);
            v.x *= a4.x; v.y *= a4.y; v.z *= a4.z; v.w *= a4.w;
            *reinterpret_cast<float4*>(&y[(rw0 + (k << 5)) * YS + f4]) = v;
        }
    }
    if (tid < VV) colpart[tid] = 0.f;
    __syncthreads();

    // Row sums T_r (one-time; float4 at stride 17 quads -> conflict-free).
    if (tid < VV) {
        const float4* p = reinterpret_cast<const float4*>(&y[tid * YS]);
        float s0 = 0.f, s1 = 0.f, s2 = 0.f, s3 = 0.f;
#pragma unroll
        for (int k = 0; k < 16; k += 4) {
            float4 v0 = p[k], v1 = p[k + 1], v2 = p[k + 2], v3 = p[k + 3];
            s0 += v0.x + v0.y + v0.z + v0.w;
            s1 += v1.x + v1.y + v1.z + v1.w;
            s2 += v2.x + v2.y + v2.z + v2.w;
            s3 += v3.x + v3.y + v3.z + v3.w;
        }
        Ts[tid] = (s0 + s1) + (s2 + s3);
    }

    // dloss_n = 2*(V*sum x^2 - sum_f (sum_i x)^2); valid since S's column
    // sums are exactly 1 (softmax axis) -> sum(S@d2) == sum(d2).
    if (b == 0 && w == 8) {
        float s1 = 0.f, s2 = 0.f;
#pragma unroll
        for (int r2 = 0; r2 < 8; ++r2) {
            s1 += red[lane + (r2 << 6)];
            s2 += red[lane + 32 + (r2 << 6)];
        }
        float t  = s1 * s1 + s2 * s2;
        float sq = (lane < 16) ? sqw[lane] : 0.f;
#pragma unroll
        for (int o = 16; o; o >>= 1) {
            t  += __shfl_down_sync(~0u, t, o);
            sq += __shfl_down_sync(~0u, sq, o);
        }
        if (lane == 0) __stcg(&g_dloss[n], 2.f * ((float)VV * sq - t));
    }
    __syncthreads();

    // ---- Phase A: warp's tile (r, c), r <= c, from triangle unrank.
    int t = b * 4 + (w >> 2);
    int r = 0;
    while (t >= 8 - r) { t -= 8 - r; ++r; }
    const int c  = r + t;
    const int c0 = ((w & 3) << 3) + (g4 << 1);  // col offset in tile (+0,+1)

    const float* __restrict__ xib = y + (r * 32 + li) * YS;   // +8k*YS
    const float* __restrict__ xjb = y + (c * 32 + c0) * YS;   // +m*YS

    float acc[8];
#pragma unroll
    for (int p = 0; p < 8; ++p) acc[p] = 0.f;

#pragma unroll 8
    for (int h = 0; h < 16; ++h) {
        float4 xi[4], xj[2];
#pragma unroll
        for (int k = 0; k < 4; ++k)
            xi[k] = *reinterpret_cast<const float4*>(xib + k * 8 * YS + h * 4);
#pragma unroll
        for (int m = 0; m < 2; ++m)
            xj[m] = *reinterpret_cast<const float4*>(xjb + m * YS + h * 4);
#pragma unroll
        for (int k = 0; k < 4; ++k)
#pragma unroll
            for (int m = 0; m < 2; ++m) {
                float s = acc[k * 2 + m];
                s += fmaxf(xi[k].x, xj[m].x);    // FMNMX (alu) + FADD (fma)
                s += fmaxf(xi[k].y, xj[m].y);
                s += fmaxf(xi[k].z, xj[m].z);
                s += fmaxf(xi[k].w, xj[m].w);
                acc[k * 2 + m] = s;
            }
    }

    // score = fma(2, acc, -(Ti+Tj)) >= 0 (relu identity); exp.
    float Ti[4], Tj[2];
#pragma unroll
    for (int k = 0; k < 4; ++k) Ti[k] = Ts[r * 32 + li + 8 * k];
#pragma unroll
    for (int m = 0; m < 2; ++m) Tj[m] = Ts[c * 32 + c0 + m];

    float e[8];
    float cp0 = 0.f, cp1 = 0.f;
#pragma unroll
    for (int k = 0; k < 4; ++k) {
        float v0 = __expf(fmaf(2.f, acc[k * 2],     -(Ti[k] + Tj[0])));
        float v1 = __expf(fmaf(2.f, acc[k * 2 + 1], -(Ti[k] + Tj[1])));
        e[k * 2] = v0; e[k * 2 + 1] = v1;
        cp0 += v0; cp1 += v1;
    }
    // Column partials: reduce over li (xor 1,2,4 stays in 8-lane group).
#pragma unroll
    for (int o = 1; o < 8; o <<= 1) {
        cp0 += __shfl_xor_sync(~0u, cp0, o);
        cp1 += __shfl_xor_sync(~0u, cp1, o);
    }
    if (li == 0) {
        atomicAdd(&colpart[c * 32 + c0],     cp0);
        atomicAdd(&colpart[c * 32 + c0 + 1], cp1);
    }
    // Row sums double as colsums of the mirrored tile (off-diag only).
    if (r != c) {
        float rp[4];
#pragma unroll
        for (int k = 0; k < 4; ++k) rp[k] = e[k * 2] + e[k * 2 + 1];
#pragma unroll
        for (int o = 8; o < 32; o <<= 1)
#pragma unroll
            for (int k = 0; k < 4; ++k)
                rp[k] += __shfl_xor_sync(~0u, rp[k], o);
        if (lane < 8)
#pragma unroll
            for (int k = 0; k < 4; ++k)
                atomicAdd(&colpart[r * 32 + li + 8 * k], rp[k]);
    }
    __syncthreads();
    if (tid < VV) {
        atomicAdd(&g_colsum[n * VV + tid], colpart[tid]);
        __threadfence();                     // publish before barrier
    }

    // ---- Single grid barrier (all 144 blocks co-resident).
    if (tid == 0) {
        __threadfence();
        if (atomicAdd(&g_c1, 1u) == NBLK - 1) g_r1 = 1u;
        else while (g_r1 == 0u) __nanosleep(64);
        __threadfence();
    }
    __syncthreads();

    if (tid < VV) invs[tid] = 1.0f / __ldcg(&g_colsum[n * VV + tid]);
    __syncthreads();

    // ---- Phase C: normalize FROM REGISTERS; write direct + mirror.
    float ivc0 = invs[c * 32 + c0], ivc1 = invs[c * 32 + c0 + 1];
    float ivr[4];
#pragma unroll
    for (int k = 0; k < 4; ++k) ivr[k] = invs[r * 32 + li + 8 * k];

    float sq2 = 0.f;
#pragma unroll
    for (int k = 0; k < 4; ++k) {
        const int gi = r * 32 + li + 8 * k;
        float S0 = e[k * 2] * ivc0, S1 = e[k * 2 + 1] * ivc1;
        *reinterpret_cast<float2*>(on + (size_t)gi * VV + c * 32 + c0) =
            make_float2(S0, S1);
        sq2 = fmaf(S0, S0, fmaf(S1, S1, sq2));
        if (r != c) {
            float M0 = e[k * 2] * ivr[k], M1 = e[k * 2 + 1] * ivr[k];
            on[(size_t)(c * 32 + c0)     * VV + gi] = M0;
            on[(size_t)(c * 32 + c0 + 1) * VV + gi] = M1;
            sq2 = fmaf(M0, M0, fmaf(M1, M1, sq2));
        }
    }
#pragma unroll
    for (int o = 16; o; o >>= 1) sq2 += __shfl_down_sync(~0u, sq2, o);
    if (lane == 0) wsum[w] = sq2;
    __syncthreads();

    // ---- Last-block finalize (graph-safe: ALL state reset each call).
    const int bid = n * 9 + b;
    if (tid == 0) {
        float tt = 0.f;
#pragma unroll
        for (int k = 0; k < 16; ++k) tt += wsum[k];
        __stcg(&g_sloss[bid], tt);
        __threadfence();
        unsigned int cdone = atomicAdd(&g_counter, 1u);
        s_flag = (cdone == NBLK - 1) ? 1u : 0u;
    }
    __syncthreads();
    if (s_flag) {
        for (int idx = tid; idx < NN * VV; idx += 512)
            __stcg(&g_colsum[idx], 0.f);     // reset for next replay
        if (w == 0) {
            __threadfence();
            float s = 0.f;
#pragma unroll
            for (int k = 0; k < 5; ++k) {
                int idx = lane + (k << 5);
                if (idx < NBLK) s += __ldcg(&g_sloss[idx]);
            }
            float dl = (lane < NN) ? __ldcg(&g_dloss[lane]) : 0.f;
#pragma unroll
            for (int o = 16; o; o >>= 1) {
                s  += __shfl_down_sync(~0u, s, o);
                dl += __shfl_down_sync(~0u, dl, o);
            }
            if (lane == 0) {
                out[NVV]     = s * (ALPHA_ / (float)NN);
                out[NVV + 1] = dl * ALPHA_;
                g_c1 = 0; g_r1 = 0; g_counter = 0;   // reset barrier state
            }
        }
    }
}

extern "C" void kernel_launch(void* const* d_in, const int* in_sizes, int n_in,
                              void* d_out, int out_size) {
    const float* x = (const float*)d_in[0];
    const float* a = (const float*)d_in[1];
    if (n_in >= 2 && in_sizes[0] == FF) {      // defensive input-order check
        const float* t = x; x = a; a = t;
    }
    float* out = (float*)d_out;

    const int smem = VV * YS * (int)sizeof(float);
    cudaFuncSetAttribute(fused_kernel,
                         cudaFuncAttributeMaxDynamicSharedMemorySize, smem);
    fused_kernel<<<dim3(9, NN), 512, smem>>>(x, a, out);
}